// round 2
// baseline (speedup 1.0000x reference)
#include <cuda_runtime.h>
#include <stdint.h>

#define NN   100000
#define INC  1024
#define HIDD 128
#define NE   1600000

// -------- scratch (device globals; no allocations allowed) --------
__device__ float g_hs[(size_t)NN * HIDD];   // h * dinv  (51.2 MB)
__device__ float g_dinv[NN];
__device__ int   g_cnt[NN];
__device__ int   g_start[NN + 1];
__device__ int   g_cursor[NN];
__device__ int   g_srcbuf[NE];

// -------- init: zero counters --------
__global__ void init_kernel() {
    int i = blockIdx.x * blockDim.x + threadIdx.x;
    if (i < NN) { g_cnt[i] = 0; g_cursor[i] = 0; }
}

// -------- count in-degrees (destinations = edge_index[1]) --------
__global__ void count_kernel(const int* __restrict__ ei) {
    int e = blockIdx.x * blockDim.x + threadIdx.x;
    if (e < NE) {
        int c = ei[NE + e];
        if ((unsigned)c < NN) atomicAdd(&g_cnt[c], 1);
    }
}

// -------- dinv = rsqrt(deg + 1)  (self-loop included) --------
__global__ void dinv_kernel() {
    int i = blockIdx.x * blockDim.x + threadIdx.x;
    if (i < NN) g_dinv[i] = rsqrtf((float)g_cnt[i] + 1.0f);
}

// -------- single-block exclusive scan over g_cnt -> g_start --------
__global__ void scan_kernel() {
    __shared__ int warpsums[32];
    __shared__ int s_carry;
    const int CH = 1024;
    int tid = threadIdx.x, lane = tid & 31, wid = tid >> 5;
    if (tid == 0) { s_carry = 0; g_start[0] = 0; }
    __syncthreads();
    int nch = (NN + CH - 1) / CH;
    for (int c = 0; c < nch; c++) {
        int i = c * CH + tid;
        int v = (i < NN) ? g_cnt[i] : 0;
        int x = v;
        #pragma unroll
        for (int off = 1; off < 32; off <<= 1) {
            int y = __shfl_up_sync(0xffffffff, x, off);
            if (lane >= off) x += y;
        }
        if (lane == 31) warpsums[wid] = x;
        __syncthreads();
        if (wid == 0) {
            int w = warpsums[lane];
            #pragma unroll
            for (int off = 1; off < 32; off <<= 1) {
                int y = __shfl_up_sync(0xffffffff, w, off);
                if (lane >= off) w += y;
            }
            warpsums[lane] = w;
        }
        __syncthreads();
        int incl = x + (wid > 0 ? warpsums[wid - 1] : 0) + s_carry;
        if (i < NN) g_start[i + 1] = incl;
        __syncthreads();
        if (tid == CH - 1) s_carry = incl;
        __syncthreads();
    }
}

// -------- fill CSR buckets with source ids --------
__global__ void fill_kernel(const int* __restrict__ ei) {
    int e = blockIdx.x * blockDim.x + threadIdx.x;
    if (e < NE) {
        int r = ei[e];
        int c = ei[NE + e];
        if ((unsigned)c < NN && (unsigned)r < NN) {
            int pos = atomicAdd(&g_cursor[c], 1);
            g_srcbuf[g_start[c] + pos] = r;
        }
    }
}

// -------- GEMM: hs = (X @ W) * dinv[row]  (BM=128,BN=128,BK=16, 256 thr) --------
__global__ __launch_bounds__(256, 2)
void gemm_kernel(const float* __restrict__ X, const float* __restrict__ W) {
    __shared__ float As[16][129];   // transposed, padded (conflict-free)
    __shared__ float Bs[16][128];
    int tid = threadIdx.x;
    int tx = tid & 15, ty = tid >> 4;
    int bm = blockIdx.x * 128;
    float acc[8][8];
    #pragma unroll
    for (int i = 0; i < 8; i++)
        #pragma unroll
        for (int j = 0; j < 8; j++) acc[i][j] = 0.0f;

    for (int k0 = 0; k0 < INC; k0 += 16) {
        // A tile: 128 rows x 16 cols = 512 float4, 2 per thread
        #pragma unroll
        for (int i = 0; i < 2; i++) {
            int id  = tid + i * 256;
            int row = id >> 2;
            int cv  = (id & 3) * 4;
            float4 a = make_float4(0.f, 0.f, 0.f, 0.f);
            if (bm + row < NN)
                a = *(const float4*)(X + (size_t)(bm + row) * INC + k0 + cv);
            As[cv + 0][row] = a.x; As[cv + 1][row] = a.y;
            As[cv + 2][row] = a.z; As[cv + 3][row] = a.w;
        }
        // B tile: 16 rows x 128 cols = 512 float4, 2 per thread
        #pragma unroll
        for (int i = 0; i < 2; i++) {
            int id  = tid + i * 256;
            int row = id >> 5;
            int cv  = (id & 31) * 4;
            *(float4*)&Bs[row][cv] =
                *(const float4*)(W + (size_t)(k0 + row) * HIDD + cv);
        }
        __syncthreads();
        #pragma unroll
        for (int k = 0; k < 16; k++) {
            float ra[8], rb[8];
            #pragma unroll
            for (int i = 0; i < 8; i++) ra[i] = As[k][ty * 8 + i];
            #pragma unroll
            for (int j = 0; j < 8; j++) rb[j] = Bs[k][tx * 8 + j];
            #pragma unroll
            for (int i = 0; i < 8; i++)
                #pragma unroll
                for (int j = 0; j < 8; j++)
                    acc[i][j] = fmaf(ra[i], rb[j], acc[i][j]);
        }
        __syncthreads();
    }
    // epilogue: hs = h * dinv[row]
    #pragma unroll
    for (int i = 0; i < 8; i++) {
        int row = bm + ty * 8 + i;
        if (row < NN) {
            float d = g_dinv[row];
            #pragma unroll
            for (int j = 0; j < 8; j += 4) {
                float4 v;
                v.x = acc[i][j + 0] * d;
                v.y = acc[i][j + 1] * d;
                v.z = acc[i][j + 2] * d;
                v.w = acc[i][j + 3] * d;
                *(float4*)(g_hs + (size_t)row * HIDD + tx * 8 + j) = v;
            }
        }
    }
}

// -------- gather-reduce: one warp per destination node --------
__global__ void gather_kernel(float* __restrict__ out) {
    int gw = (blockIdx.x * blockDim.x + threadIdx.x) >> 5;
    int lane = threadIdx.x & 31;
    if (gw >= NN) return;
    const float4* hs4 = (const float4*)g_hs;
    int s0 = g_start[gw], s1 = g_start[gw + 1];
    // self-loop term (hs already carries dinv[src])
    float4 acc = hs4[(size_t)gw * 32 + lane];
    for (int j = s0; j < s1; j++) {
        int src = g_srcbuf[j];
        float4 v = hs4[(size_t)src * 32 + lane];
        acc.x += v.x; acc.y += v.y; acc.z += v.z; acc.w += v.w;
    }
    float d = g_dinv[gw];
    float4 r = make_float4(acc.x * d, acc.y * d, acc.z * d, acc.w * d);
    ((float4*)out)[(size_t)gw * 32 + lane] = r;
}

extern "C" void kernel_launch(void* const* d_in, const int* in_sizes, int n_in,
                              void* d_out, int out_size) {
    const float* X  = (const float*)d_in[0];
    const float* W  = (const float*)d_in[1];
    const int*   ei = (const int*)d_in[2];
    float* out = (float*)d_out;

    init_kernel <<<(NN + 255) / 256, 256>>>();
    count_kernel<<<(NE + 255) / 256, 256>>>(ei);
    dinv_kernel <<<(NN + 255) / 256, 256>>>();
    scan_kernel <<<1, 1024>>>();
    fill_kernel <<<(NE + 255) / 256, 256>>>(ei);
    gemm_kernel <<<(NN + 127) / 128, 256>>>(X, W);
    gather_kernel<<<(NN * 32 + 255) / 256, 256>>>(out);
}

// round 3
// speedup vs baseline: 1.0006x; 1.0006x over previous
#include <cuda_runtime.h>
#include <stdint.h>

#define NN   100000
#define INC  1024
#define HIDD 128
#define NE   1600000

// -------- scratch (device globals; no allocations allowed) --------
__device__ float g_hs[(size_t)NN * HIDD];   // h * dinv  (51.2 MB)
__device__ float g_dinv[NN];
__device__ int   g_cnt[NN];
__device__ int   g_start[NN + 1];
__device__ int   g_cursor[NN];
__device__ int   g_srcbuf[NE];

// -------- init: zero counters --------
__global__ void init_kernel() {
    int i = blockIdx.x * blockDim.x + threadIdx.x;
    if (i < NN) { g_cnt[i] = 0; g_cursor[i] = 0; }
}

// -------- count in-degrees (destinations = edge_index[1]) --------
__global__ void count_kernel(const int* __restrict__ ei) {
    int e = blockIdx.x * blockDim.x + threadIdx.x;
    if (e < NE) {
        int c = ei[NE + e];
        if ((unsigned)c < NN) atomicAdd(&g_cnt[c], 1);
    }
}

// -------- dinv = rsqrt(deg + 1)  (self-loop included) --------
__global__ void dinv_kernel() {
    int i = blockIdx.x * blockDim.x + threadIdx.x;
    if (i < NN) g_dinv[i] = rsqrtf((float)g_cnt[i] + 1.0f);
}

// -------- single-block exclusive scan over g_cnt -> g_start --------
__global__ void scan_kernel() {
    __shared__ int warpsums[32];
    __shared__ int s_carry;
    const int CH = 1024;
    int tid = threadIdx.x, lane = tid & 31, wid = tid >> 5;
    if (tid == 0) { s_carry = 0; g_start[0] = 0; }
    __syncthreads();
    int nch = (NN + CH - 1) / CH;
    for (int c = 0; c < nch; c++) {
        int i = c * CH + tid;
        int v = (i < NN) ? g_cnt[i] : 0;
        int x = v;
        #pragma unroll
        for (int off = 1; off < 32; off <<= 1) {
            int y = __shfl_up_sync(0xffffffff, x, off);
            if (lane >= off) x += y;
        }
        if (lane == 31) warpsums[wid] = x;
        __syncthreads();
        if (wid == 0) {
            int w = warpsums[lane];
            #pragma unroll
            for (int off = 1; off < 32; off <<= 1) {
                int y = __shfl_up_sync(0xffffffff, w, off);
                if (lane >= off) w += y;
            }
            warpsums[lane] = w;
        }
        __syncthreads();
        int incl = x + (wid > 0 ? warpsums[wid - 1] : 0) + s_carry;
        if (i < NN) g_start[i + 1] = incl;
        __syncthreads();
        if (tid == CH - 1) s_carry = incl;
        __syncthreads();
    }
}

// -------- fill CSR buckets with source ids --------
__global__ void fill_kernel(const int* __restrict__ ei) {
    int e = blockIdx.x * blockDim.x + threadIdx.x;
    if (e < NE) {
        int r = ei[e];
        int c = ei[NE + e];
        if ((unsigned)c < NN && (unsigned)r < NN) {
            int pos = atomicAdd(&g_cursor[c], 1);
            g_srcbuf[g_start[c] + pos] = r;
        }
    }
}

// -------- GEMM: hs = (X @ W) * dinv[row]  (BM=128,BN=128,BK=16, 256 thr) --------
__global__ __launch_bounds__(256, 2)
void gemm_kernel(const float* __restrict__ X, const float* __restrict__ W) {
    __shared__ float As[16][129];   // transposed, padded (conflict-free)
    __shared__ float Bs[16][128];
    int tid = threadIdx.x;
    int tx = tid & 15, ty = tid >> 4;
    int bm = blockIdx.x * 128;
    float acc[8][8];
    #pragma unroll
    for (int i = 0; i < 8; i++)
        #pragma unroll
        for (int j = 0; j < 8; j++) acc[i][j] = 0.0f;

    for (int k0 = 0; k0 < INC; k0 += 16) {
        // A tile: 128 rows x 16 cols = 512 float4, 2 per thread
        #pragma unroll
        for (int i = 0; i < 2; i++) {
            int id  = tid + i * 256;
            int row = id >> 2;
            int cv  = (id & 3) * 4;
            float4 a = make_float4(0.f, 0.f, 0.f, 0.f);
            if (bm + row < NN)
                a = *(const float4*)(X + (size_t)(bm + row) * INC + k0 + cv);
            As[cv + 0][row] = a.x; As[cv + 1][row] = a.y;
            As[cv + 2][row] = a.z; As[cv + 3][row] = a.w;
        }
        // B tile: 16 rows x 128 cols = 512 float4, 2 per thread
        #pragma unroll
        for (int i = 0; i < 2; i++) {
            int id  = tid + i * 256;
            int row = id >> 5;
            int cv  = (id & 31) * 4;
            *(float4*)&Bs[row][cv] =
                *(const float4*)(W + (size_t)(k0 + row) * HIDD + cv);
        }
        __syncthreads();
        #pragma unroll
        for (int k = 0; k < 16; k++) {
            float ra[8], rb[8];
            #pragma unroll
            for (int i = 0; i < 8; i++) ra[i] = As[k][ty * 8 + i];
            #pragma unroll
            for (int j = 0; j < 8; j++) rb[j] = Bs[k][tx * 8 + j];
            #pragma unroll
            for (int i = 0; i < 8; i++)
                #pragma unroll
                for (int j = 0; j < 8; j++)
                    acc[i][j] = fmaf(ra[i], rb[j], acc[i][j]);
        }
        __syncthreads();
    }
    // epilogue: hs = h * dinv[row]
    #pragma unroll
    for (int i = 0; i < 8; i++) {
        int row = bm + ty * 8 + i;
        if (row < NN) {
            float d = g_dinv[row];
            #pragma unroll
            for (int j = 0; j < 8; j += 4) {
                float4 v;
                v.x = acc[i][j + 0] * d;
                v.y = acc[i][j + 1] * d;
                v.z = acc[i][j + 2] * d;
                v.w = acc[i][j + 3] * d;
                *(float4*)(g_hs + (size_t)row * HIDD + tx * 8 + j) = v;
            }
        }
    }
}

// -------- gather-reduce: one warp per destination node --------
__global__ void gather_kernel(float* __restrict__ out) {
    int gw = (blockIdx.x * blockDim.x + threadIdx.x) >> 5;
    int lane = threadIdx.x & 31;
    if (gw >= NN) return;
    const float4* hs4 = (const float4*)g_hs;
    int s0 = g_start[gw], s1 = g_start[gw + 1];
    // self-loop term (hs already carries dinv[src])
    float4 acc = hs4[(size_t)gw * 32 + lane];
    for (int j = s0; j < s1; j++) {
        int src = g_srcbuf[j];
        float4 v = hs4[(size_t)src * 32 + lane];
        acc.x += v.x; acc.y += v.y; acc.z += v.z; acc.w += v.w;
    }
    float d = g_dinv[gw];
    float4 r = make_float4(acc.x * d, acc.y * d, acc.z * d, acc.w * d);
    ((float4*)out)[(size_t)gw * 32 + lane] = r;
}

extern "C" void kernel_launch(void* const* d_in, const int* in_sizes, int n_in,
                              void* d_out, int out_size) {
    const float* X  = (const float*)d_in[0];
    const float* W  = (const float*)d_in[1];
    const int*   ei = (const int*)d_in[2];
    float* out = (float*)d_out;

    init_kernel <<<(NN + 255) / 256, 256>>>();
    count_kernel<<<(NE + 255) / 256, 256>>>(ei);
    dinv_kernel <<<(NN + 255) / 256, 256>>>();
    scan_kernel <<<1, 1024>>>();
    fill_kernel <<<(NE + 255) / 256, 256>>>(ei);
    gemm_kernel <<<(NN + 127) / 128, 256>>>(X, W);
    gather_kernel<<<(NN * 32 + 255) / 256, 256>>>(out);
}